// round 13
// baseline (speedup 1.0000x reference)
#include <cuda_runtime.h>
#include <cuda_bf16.h>
#include <cstdint>

#define BB 32
#define CC 384
#define TT 512
#define MAX_FRAMES 6656   // TT * 13
#define G 4               // channels per expand block
#define CGROUPS (CC / G)  // 96
#define NT 256
#define NSLOT (MAX_FRAMES / 4)   // 1664 float4 slots

// out layout in d_out (float):
//   [0, BB*CC*MAX_FRAMES)            : out (b, c, pos)
//   [+0, +BB*MAX_FRAMES)             : pitch (b, pos)
//   [+0, +BB)                        : frame_lengths (as float value)
#define OUT_ELEMS   ((size_t)BB * CC * MAX_FRAMES)
#define PITCH_OFF   OUT_ELEMS
#define LEN_OFF     (OUT_ELEMS + (size_t)BB * MAX_FRAMES)

// ---------------------------------------------------------------------------
// Single fused kernel. grid = (CGROUPS+1, BB), 256 threads.
//   cg <  CGROUPS : expand G=4 channels of x
//   cg == CGROUPS : write pitch + frame_lengths
// Per block: repeat counts + shfl scan + scatter tok over [0,L) only.
// Store loop split into [full gather | boundary slot | pure zero stream];
// the zero region never touches tok, so no tail init is needed.
// All output stores are streaming (.cs) — output is never re-read.
// ---------------------------------------------------------------------------
__global__ void __launch_bounds__(NT) fused_kernel(
    const float* __restrict__ x,
    const float* __restrict__ notepitch,
    const float* __restrict__ duration,
    float* __restrict__ out)
{
    const int cg  = blockIdx.x;
    const int b   = blockIdx.y;
    const int tid = threadIdx.x;
    const int lane = tid & 31, wid = tid >> 5;

    __shared__ float xs[G * TT];                     // 8 KB (x rows OR pitch row)
    __shared__ unsigned short tok_s[MAX_FRAMES];     // 13 KB
    __shared__ int wsum[8];
    __shared__ int L_s;

    // ---- repeat counts for elements e0=2*tid, e1=2*tid+1 (exact fp32) ----
    const float2 d2 = ((const float2*)(duration + b * TT))[tid];
    int r0, r1;
    {
        const float fm = __fsub_rn(__fmul_rn(44100.0f, d2.x), 1024.0f);
        float rr;
        if (fm > 0.0f) rr = fmaxf(__fmul_rn(fm, (1.0f / 256.0f)), 1.0f);
        else           rr = (d2.x == 0.0f) ? 0.0f : 1.0f;
        r0 = (int)rr;
    }
    {
        const float fm = __fsub_rn(__fmul_rn(44100.0f, d2.y), 1024.0f);
        float rr;
        if (fm > 0.0f) rr = fmaxf(__fmul_rn(fm, (1.0f / 256.0f)), 1.0f);
        else           rr = (d2.y == 0.0f) ? 0.0f : 1.0f;
        r1 = (int)rr;
    }

    // ---- load xs: x rows (expand blocks) or notepitch row (pitch block) ----
    if (cg < CGROUPS) {
        const float4* xsrc = (const float4*)(x + ((size_t)b * CC + (size_t)cg * G) * TT);
        float4* xdst = (float4*)xs;
        #pragma unroll
        for (int i = tid; i < G * TT / 4; i += NT) xdst[i] = xsrc[i];
    } else {
        if (tid < TT / 4)
            ((float4*)xs)[tid] = ((const float4*)(notepitch + b * TT))[tid];
    }

    // ---- inclusive scan of pair sums (256 threads cover 512 elements) ----
    const int pair = r0 + r1;
    int v = pair;
    #pragma unroll
    for (int o = 1; o < 32; o <<= 1) {
        int n = __shfl_up_sync(0xFFFFFFFFu, v, o);
        if (lane >= o) v += n;
    }
    if (lane == 31) wsum[wid] = v;
    __syncthreads();
    if (wid == 0 && lane < 8) {
        int s = wsum[lane];
        #pragma unroll
        for (int o = 1; o < 8; o <<= 1) {
            int n = __shfl_up_sync(0x000000FFu, s, o);
            if (lane >= o) s += n;
        }
        wsum[lane] = s;
    }
    __syncthreads();
    const int base = (wid > 0) ? wsum[wid - 1] : 0;
    const int pair_incl = base + v;            // cum over pairs, inclusive
    const int e0_start  = pair_incl - pair;    // exclusive prefix of e0
    if (tid == NT - 1) L_s = pair_incl;
    __syncthreads();

    const int L = L_s;                // 512 <= L <= 6656 for this data

    // ---- scatter-fill tok map over [0, L) only ----
    const int e0 = 2 * tid, e1 = 2 * tid + 1;
    for (int p = e0_start; p < e0_start + r0; p++)
        tok_s[p] = (unsigned short)e0;
    for (int p = e0_start + r0; p < pair_incl; p++)
        tok_s[p] = (unsigned short)e1;
    __syncthreads();

    const int ifull = L >> 2;          // slots entirely < L
    const int izero = (L + 3) >> 2;    // first all-zero slot
    const float4 z4 = make_float4(0.0f, 0.0f, 0.0f, 0.0f);

    if (cg == CGROUPS) {
        // ---- pitch + frame_lengths ----
        if (tid == 0) out[LEN_OFF + b] = (float)L;
        float4* pout = (float4*)(out + PITCH_OFF + (size_t)b * MAX_FRAMES);
        for (int i = tid; i < ifull; i += NT) {
            const uint2 tw = ((const uint2*)tok_s)[i];
            float4 v4;
            v4.x = (float)(int)xs[tw.x & 0xFFFF];
            v4.y = (float)(int)xs[tw.x >> 16];
            v4.z = (float)(int)xs[tw.y & 0xFFFF];
            v4.w = (float)(int)xs[tw.y >> 16];
            __stcs(pout + i, v4);
        }
        if (tid == 0 && (L & 3)) {     // boundary slot
            float4 v4 = z4;
            const int pos = ifull << 2;
            if (pos + 0 < L) v4.x = (float)(int)xs[tok_s[pos + 0]];
            if (pos + 1 < L) v4.y = (float)(int)xs[tok_s[pos + 1]];
            if (pos + 2 < L) v4.z = (float)(int)xs[tok_s[pos + 2]];
            __stcs(pout + ifull, v4);
        }
        for (int i = izero + tid; i < NSLOT; i += NT)
            __stcs(pout + i, z4);
        return;
    }

    // ---- expand: G channels ----
    float* outbase = out + ((size_t)b * CC + (size_t)cg * G) * MAX_FRAMES;

    // region 1: full gather slots, unconditional
    for (int i = tid; i < ifull; i += NT) {
        const uint2 tw = ((const uint2*)tok_s)[i];
        const int t0 = tw.x & 0xFFFF, t1 = tw.x >> 16;
        const int t2 = tw.y & 0xFFFF, t3 = tw.y >> 16;
        #pragma unroll
        for (int c = 0; c < G; c++) {
            const float* xc = xs + c * TT;
            float4 v4 = make_float4(xc[t0], xc[t1], xc[t2], xc[t3]);
            __stcs((float4*)(outbase + (size_t)c * MAX_FRAMES) + i, v4);
        }
    }

    // region 2: single boundary slot (only if L not multiple of 4)
    if (tid == 0 && (L & 3)) {
        const int pos = ifull << 2;
        const int m = L & 3;           // 1..3 valid elements
        #pragma unroll
        for (int c = 0; c < G; c++) {
            const float* xc = xs + c * TT;
            float4 v4 = z4;
            v4.x = xc[tok_s[pos + 0]];
            if (m > 1) v4.y = xc[tok_s[pos + 1]];
            if (m > 2) v4.z = xc[tok_s[pos + 2]];
            __stcs((float4*)(outbase + (size_t)c * MAX_FRAMES) + ifull, v4);
        }
    }

    // region 3: pure zero stream (no tok reads, no compares)
    for (int i = izero + tid; i < NSLOT; i += NT) {
        #pragma unroll
        for (int c = 0; c < G; c++)
            __stcs((float4*)(outbase + (size_t)c * MAX_FRAMES) + i, z4);
    }
}

extern "C" void kernel_launch(void* const* d_in, const int* in_sizes, int n_in,
                              void* d_out, int out_size)
{
    const float* x         = (const float*)d_in[0];
    const float* notepitch = (const float*)d_in[1];
    const float* duration  = (const float*)d_in[2];
    // d_in[3] = x_lengths (unused by the reference)
    float* out = (float*)d_out;

    fused_kernel<<<dim3(CGROUPS + 1, BB), NT>>>(x, notepitch, duration, out);
}

// round 14
// speedup vs baseline: 1.0261x; 1.0261x over previous
#include <cuda_runtime.h>
#include <cuda_bf16.h>
#include <cstdint>

#define BB 32
#define CC 384
#define TT 512
#define MAX_FRAMES 6656   // TT * 13
#define G 4               // channels per expand block
#define CGROUPS (CC / G)  // 96

// out layout in d_out (float):
//   [0, BB*CC*MAX_FRAMES)            : out (b, c, pos)
//   [+0, +BB*MAX_FRAMES)             : pitch (b, pos)
//   [+0, +BB)                        : frame_lengths (as float value)
#define OUT_ELEMS   ((size_t)BB * CC * MAX_FRAMES)
#define PITCH_OFF   OUT_ELEMS
#define LEN_OFF     (OUT_ELEMS + (size_t)BB * MAX_FRAMES)

// ---------------------------------------------------------------------------
// Single fused kernel. grid = (CGROUPS+1, BB), 256 threads.
//   cg <  CGROUPS : expand G channels of x
//   cg == CGROUPS : write pitch + frame_lengths
// Every block independently recomputes the per-batch repeat counts, an
// inclusive scan (registers + shfl), and scatter-fills the tok map in SMEM.
// Output stores use streaming (.cs) hints — output is never re-read.
// This is the empirically fastest shape (R11): write-bandwidth-bound at
// ~5.9 TB/s effective; all store-loop restructurings regressed or were
// neutral (R10, R12, R13).
// ---------------------------------------------------------------------------
__global__ void __launch_bounds__(256) fused_kernel(
    const float* __restrict__ x,
    const float* __restrict__ notepitch,
    const float* __restrict__ duration,
    float* __restrict__ out)
{
    const int cg  = blockIdx.x;
    const int b   = blockIdx.y;
    const int tid = threadIdx.x;
    const int lane = tid & 31, wid = tid >> 5;

    __shared__ float xs[G * TT];                     // 8 KB (x rows OR pitch row)
    __shared__ unsigned short tok_s[MAX_FRAMES];     // 13 KB
    __shared__ int wsum[8];
    __shared__ int L_s;

    // ---- repeat counts for elements e0=2*tid, e1=2*tid+1 (exact fp32) ----
    const float2 d2 = ((const float2*)(duration + b * TT))[tid];
    int r0, r1;
    {
        const float fm = __fsub_rn(__fmul_rn(44100.0f, d2.x), 1024.0f);
        float rr;
        if (fm > 0.0f) rr = fmaxf(__fmul_rn(fm, (1.0f / 256.0f)), 1.0f);
        else           rr = (d2.x == 0.0f) ? 0.0f : 1.0f;
        r0 = (int)rr;
    }
    {
        const float fm = __fsub_rn(__fmul_rn(44100.0f, d2.y), 1024.0f);
        float rr;
        if (fm > 0.0f) rr = fmaxf(__fmul_rn(fm, (1.0f / 256.0f)), 1.0f);
        else           rr = (d2.y == 0.0f) ? 0.0f : 1.0f;
        r1 = (int)rr;
    }

    // ---- init tok map to 511 (searchsorted clamp value for pos >= L) ----
    {
        unsigned int* tw = (unsigned int*)tok_s;
        #pragma unroll
        for (int i = tid; i < MAX_FRAMES / 2; i += 256)
            tw[i] = (511u << 16) | 511u;
    }

    // ---- load xs: x rows (expand blocks) or notepitch row (pitch block) ----
    if (cg < CGROUPS) {
        const float4* xsrc = (const float4*)(x + ((size_t)b * CC + (size_t)cg * G) * TT);
        float4* xdst = (float4*)xs;
        #pragma unroll
        for (int i = tid; i < G * TT / 4; i += 256) xdst[i] = xsrc[i];
    } else {
        const float4* psrc = (const float4*)(notepitch + b * TT);
        float4* pdst = (float4*)xs;
        #pragma unroll
        for (int i = tid; i < TT / 4; i += 256) pdst[i] = psrc[i];
    }

    // ---- inclusive scan of pair sums (256 threads cover 512 elements) ----
    const int pair = r0 + r1;
    int v = pair;
    #pragma unroll
    for (int o = 1; o < 32; o <<= 1) {
        int n = __shfl_up_sync(0xFFFFFFFFu, v, o);
        if (lane >= o) v += n;
    }
    if (lane == 31) wsum[wid] = v;
    __syncthreads();
    if (wid == 0 && lane < 8) {
        int s = wsum[lane];
        #pragma unroll
        for (int o = 1; o < 8; o <<= 1) {
            int n = __shfl_up_sync(0x000000FFu, s, o);
            if (lane >= o) s += n;
        }
        wsum[lane] = s;
    }
    __syncthreads();
    const int base = (wid > 0) ? wsum[wid - 1] : 0;
    const int pair_incl = base + v;            // cum over pairs, inclusive
    const int e0_start  = pair_incl - pair;    // exclusive prefix of e0
    if (tid == 255) L_s = pair_incl;           // total frame length
    __syncthreads();

    // ---- scatter-fill tok map: tok[p] = e for p in [start_e, end_e) ----
    const int e0 = 2 * tid, e1 = 2 * tid + 1;
    for (int p = e0_start; p < e0_start + r0; p++)
        tok_s[p] = (unsigned short)e0;
    for (int p = e0_start + r0; p < pair_incl; p++)
        tok_s[p] = (unsigned short)e1;
    __syncthreads();

    const int L = L_s;

    if (cg == CGROUPS) {
        // ---- pitch + frame_lengths ----
        if (tid == 0) out[LEN_OFF + b] = (float)L;
        float4* pout = (float4*)(out + PITCH_OFF + (size_t)b * MAX_FRAMES);
        for (int i = tid; i < MAX_FRAMES / 4; i += 256) {
            const int pos = i << 2;
            const uint2 tw = ((const uint2*)tok_s)[i];
            const int t0 = tw.x & 0xFFFF, t1 = tw.x >> 16;
            const int t2 = tw.y & 0xFFFF, t3 = tw.y >> 16;
            float4 v4;
            v4.x = (pos + 0 < L) ? (float)(int)xs[t0] : 0.0f;
            v4.y = (pos + 1 < L) ? (float)(int)xs[t1] : 0.0f;
            v4.z = (pos + 2 < L) ? (float)(int)xs[t2] : 0.0f;
            v4.w = (pos + 3 < L) ? (float)(int)xs[t3] : 0.0f;
            __stcs(pout + i, v4);
        }
        return;
    }

    // ---- expand: G channels, float4 streaming stores ----
    float* outbase = out + ((size_t)b * CC + (size_t)cg * G) * MAX_FRAMES;

    for (int i = tid; i < MAX_FRAMES / 4; i += 256) {   // 1664 float4 slots
        const int pos = i << 2;
        const uint2 tw = ((const uint2*)tok_s)[i];
        const int t0 = tw.x & 0xFFFF, t1 = tw.x >> 16;
        const int t2 = tw.y & 0xFFFF, t3 = tw.y >> 16;

        if (pos + 3 < L) {
            #pragma unroll
            for (int c = 0; c < G; c++) {
                const float* xc = xs + c * TT;
                float4 v4 = make_float4(xc[t0], xc[t1], xc[t2], xc[t3]);
                __stcs((float4*)(outbase + (size_t)c * MAX_FRAMES) + i, v4);
            }
        } else if (pos >= L) {
            const float4 z = make_float4(0.0f, 0.0f, 0.0f, 0.0f);
            #pragma unroll
            for (int c = 0; c < G; c++)
                __stcs((float4*)(outbase + (size_t)c * MAX_FRAMES) + i, z);
        } else {
            #pragma unroll
            for (int c = 0; c < G; c++) {
                const float* xc = xs + c * TT;
                float4 v4;
                v4.x = (pos + 0 < L) ? xc[t0] : 0.0f;
                v4.y = (pos + 1 < L) ? xc[t1] : 0.0f;
                v4.z = (pos + 2 < L) ? xc[t2] : 0.0f;
                v4.w = (pos + 3 < L) ? xc[t3] : 0.0f;
                __stcs((float4*)(outbase + (size_t)c * MAX_FRAMES) + i, v4);
            }
        }
    }
}

extern "C" void kernel_launch(void* const* d_in, const int* in_sizes, int n_in,
                              void* d_out, int out_size)
{
    const float* x         = (const float*)d_in[0];
    const float* notepitch = (const float*)d_in[1];
    const float* duration  = (const float*)d_in[2];
    // d_in[3] = x_lengths (unused by the reference)
    float* out = (float*)d_out;

    fused_kernel<<<dim3(CGROUPS + 1, BB), 256>>>(x, notepitch, duration, out);
}